// round 5
// baseline (speedup 1.0000x reference)
#include <cuda_runtime.h>

#define NB 4
#define H  256
#define W  448
#define C  64
#define HW (H * W)
#define NHW (NB * HW)

// NHWC accumulation scratch (4 consecutive channels 16B-contiguous for
// red.global.add.v4.f32) + separate norm plane. Static __device__ arrays are
// the allocation-guard-safe scratch mechanism.
__device__ __align__(16) float g_scratch[(size_t)NHW * C];
__device__ __align__(16) float g_norm[NHW];

__device__ __forceinline__ void red_add_v4(float* a, float x, float y, float z, float w) {
    asm volatile("red.global.add.v4.f32 [%0], {%1, %2, %3, %4};"
                 :: "l"(a), "f"(x), "f"(y), "f"(z), "f"(w) : "memory");
}
__device__ __forceinline__ void red_add_f32(float* a, float v) {
    asm volatile("red.global.add.f32 [%0], %1;"
                 :: "l"(a), "f"(v) : "memory");
}

__global__ void zero_kernel() {
    const int SF4 = NHW * C / 4;
    const int NF4 = NHW / 4;
    const int total = SF4 + NF4;
    float4 z = make_float4(0.f, 0.f, 0.f, 0.f);
    for (int i = blockIdx.x * blockDim.x + threadIdx.x; i < total;
         i += gridDim.x * blockDim.x) {
        if (i < SF4) reinterpret_cast<float4*>(g_scratch)[i] = z;
        else         reinterpret_cast<float4*>(g_norm)[i - SF4] = z;
    }
}

__global__ void scatter_kernel(const float* __restrict__ inp,
                               const float* __restrict__ flow,
                               const float* __restrict__ metric) {
    int idx = blockIdx.x * blockDim.x + threadIdx.x;
    if (idx >= NHW) return;
    int x  = idx % W;
    int ny = idx / W;
    int y  = ny % H;
    int n  = ny / H;
    int pix_in = y * W + x;

    float fx = (float)x + flow[(n * 2 + 0) * HW + pix_in];
    float fy = (float)y + flow[(n * 2 + 1) * HW + pix_in];
    float m  = expf(metric[n * HW + pix_in]);

    float x0f = floorf(fx), y0f = floorf(fy);
    int   ix0 = (int)x0f,   iy0 = (int)y0f;
    float ax = fx - x0f, ay = fy - y0f;

    float wts[4] = { (1.f - ax) * (1.f - ay) * m,
                     ax         * (1.f - ay) * m,
                     (1.f - ax) * ay         * m,
                     ax         * ay         * m };
    int xs[4] = { ix0, ix0 + 1, ix0,     ix0 + 1 };
    int ys[4] = { iy0, iy0,     iy0 + 1, iy0 + 1 };

    int   cnt = 0;
    int   base[4];
    float cw[4];
    int nbase = n * HW;
#pragma unroll
    for (int k = 0; k < 4; k++) {
        bool valid = (xs[k] >= 0) & (xs[k] < W) & (ys[k] >= 0) & (ys[k] < H);
        if (valid) {
            int pix = nbase + ys[k] * W + xs[k];
            red_add_f32(&g_norm[pix], wts[k]);
            base[cnt] = pix * C;
            cw[cnt]   = wts[k];
            cnt++;
        }
    }

    const float* ip0 = inp + (size_t)n * C * HW + pix_in;
#pragma unroll 4
    for (int q = 0; q < 16; q++) {
        int c = q * 4;
        const float* ip = ip0 + (size_t)c * HW;
        float v0 = ip[0 * HW];
        float v1 = ip[1 * HW];
        float v2 = ip[2 * HW];
        float v3 = ip[3 * HW];
        for (int k = 0; k < cnt; k++) {
            float wv = cw[k];
            red_add_v4(&g_scratch[base[k] + c], v0 * wv, v1 * wv, v2 * wv, v3 * wv);
        }
    }
}

__global__ void normalize_kernel(float* __restrict__ out) {
    int idx = blockIdx.x * blockDim.x + threadIdx.x;
    if (idx >= NHW) return;
    float nv  = g_norm[idx];
    float inv = (nv == 0.f) ? 1.f : (1.f / nv);

    int x  = idx % W;
    int ny = idx / W;
    int y  = ny % H;
    int n  = ny / H;

    const float4* s  = reinterpret_cast<const float4*>(g_scratch) + (size_t)idx * (C / 4);
    float*        op = out + (size_t)n * C * HW + y * W + x;
#pragma unroll
    for (int q = 0; q < 16; q++) {
        float4 v = s[q];
        op[(4 * q + 0) * HW] = v.x * inv;
        op[(4 * q + 1) * HW] = v.y * inv;
        op[(4 * q + 2) * HW] = v.z * inv;
        op[(4 * q + 3) * HW] = v.w * inv;
    }
}

extern "C" void kernel_launch(void* const* d_in, const int* in_sizes, int n_in,
                              void* d_out, int out_size) {
    const float* inp    = (const float*)d_in[0];
    const float* flow   = (const float*)d_in[1];
    const float* metric = (const float*)d_in[2];
    float* out = (float*)d_out;

    zero_kernel<<<592, 256>>>();   // 148 SMs * 4 blocks, grid-stride
    scatter_kernel<<<(NHW + 255) / 256, 256>>>(inp, flow, metric);
    normalize_kernel<<<(NHW + 255) / 256, 256>>>(out);
}

// round 11
// speedup vs baseline: 1.6743x; 1.6743x over previous
#include <cuda_runtime.h>

#define NB 4
#define H  256
#define W  448
#define C  64
#define HW (H * W)
#define NHW (NB * HW)
#define TILE 32   // pixels per block in scatter (HW % TILE == 0, so no batch-crossing)
#define PADC (C + 4)  // row stride 68 floats = 272B: 16B-aligned float4 rows, bank-skewed

// NHWC accumulation scratch (4 consecutive channels 16B-contiguous for
// red.global.add.v4.f32) + separate norm plane.
__device__ __align__(16) float g_scratch[(size_t)NHW * C];
__device__ __align__(16) float g_norm[NHW];

__device__ __forceinline__ void red_add_v4(float* a, float x, float y, float z, float w) {
    asm volatile("red.global.add.v4.f32 [%0], {%1, %2, %3, %4};"
                 :: "l"(a), "f"(x), "f"(y), "f"(z), "f"(w) : "memory");
}
__device__ __forceinline__ void red_add_f32(float* a, float v) {
    asm volatile("red.global.add.f32 [%0], %1;"
                 :: "l"(a), "f"(v) : "memory");
}

__global__ void zero_kernel() {
    const int SF4 = NHW * C / 4;
    const int NF4 = NHW / 4;
    const int total = SF4 + NF4;
    float4 z = make_float4(0.f, 0.f, 0.f, 0.f);
    for (int i = blockIdx.x * blockDim.x + threadIdx.x; i < total;
         i += gridDim.x * blockDim.x) {
        if (i < SF4) reinterpret_cast<float4*>(g_scratch)[i] = z;
        else         reinterpret_cast<float4*>(g_norm)[i - SF4] = z;
    }
}

// Warp-cooperative scatter: block stages TILE=32 pixels x 64 ch in smem
// (coalesced NCHW loads), then 16 lanes handle one pixel so each corner's
// atomic update is a 256B-contiguous red.global.v4 burst.
__global__ void scatter_kernel(const float* __restrict__ inp,
                               const float* __restrict__ flow,
                               const float* __restrict__ metric) {
    __shared__ __align__(16) float s_in[TILE][PADC];

    const int tile = blockIdx.x;
    const int gp0  = tile * TILE;         // global linear pixel (n*HW + pin)
    const int n    = gp0 / HW;            // constant per tile (HW % TILE == 0)
    const int pin0 = gp0 - n * HW;

    const int tid  = threadIdx.x;
    const int w    = tid >> 5;
    const int lane = tid & 31;

    // ---- Load phase: warp w loads channels [8w, 8w+8), 32 px per 128B line ----
    const float* ibase = inp + (size_t)n * C * HW + pin0;
#pragma unroll
    for (int cc = 0; cc < 8; cc++) {
        int c = w * 8 + cc;
        s_in[lane][c] = ibase[(size_t)c * HW + lane];
    }
    __syncthreads();

    // ---- Scatter phase: 2 passes x (8 warps x 2 px); 16 lanes per pixel ----
    const float* fxp = flow + (size_t)(n * 2 + 0) * HW;
    const float* fyp = flow + (size_t)(n * 2 + 1) * HW;
    const float* mp  = metric + (size_t)n * HW;
    const int q = lane & 15;              // quad index (channel 4q..4q+3)

#pragma unroll
    for (int pass = 0; pass < 2; pass++) {
        int lp  = pass * 16 + w * 2 + (lane >> 4);   // local pixel 0..31
        int pin = pin0 + lp;
        int x = pin % W;
        int y = pin / W;

        float fx = (float)x + fxp[pin];   // broadcast load (16 lanes same addr)
        float fy = (float)y + fyp[pin];
        float m  = expf(mp[pin]);

        float x0f = floorf(fx), y0f = floorf(fy);
        int   ix0 = (int)x0f,   iy0 = (int)y0f;
        float ax = fx - x0f, ay = fy - y0f;

        float wts[4] = { (1.f - ax) * (1.f - ay) * m,
                         ax         * (1.f - ay) * m,
                         (1.f - ax) * ay         * m,
                         ax         * ay         * m };
        int xs[4] = { ix0, ix0 + 1, ix0,     ix0 + 1 };
        int ys[4] = { iy0, iy0,     iy0 + 1, iy0 + 1 };

        float4 v = *reinterpret_cast<const float4*>(&s_in[lp][q * 4]);

#pragma unroll
        for (int k = 0; k < 4; k++) {
            bool valid = (xs[k] >= 0) & (xs[k] < W) & (ys[k] >= 0) & (ys[k] < H);
            if (valid) {
                int   tpix = n * HW + ys[k] * W + xs[k];
                float wk   = wts[k];
                if (q == k) red_add_f32(&g_norm[tpix], wk);  // 1 lane per corner
                red_add_v4(&g_scratch[(size_t)tpix * C + q * 4],
                           v.x * wk, v.y * wk, v.z * wk, v.w * wk);
            }
        }
    }
}

__global__ void normalize_kernel(float* __restrict__ out) {
    int idx = blockIdx.x * blockDim.x + threadIdx.x;
    if (idx >= NHW) return;
    float nv  = g_norm[idx];
    float inv = (nv == 0.f) ? 1.f : (1.f / nv);

    int x  = idx % W;
    int ny = idx / W;
    int y  = ny % H;
    int n  = ny / H;

    const float4* s  = reinterpret_cast<const float4*>(g_scratch) + (size_t)idx * (C / 4);
    float*        op = out + (size_t)n * C * HW + y * W + x;
#pragma unroll
    for (int q = 0; q < 16; q++) {
        float4 v = s[q];
        op[(4 * q + 0) * HW] = v.x * inv;
        op[(4 * q + 1) * HW] = v.y * inv;
        op[(4 * q + 2) * HW] = v.z * inv;
        op[(4 * q + 3) * HW] = v.w * inv;
    }
}

extern "C" void kernel_launch(void* const* d_in, const int* in_sizes, int n_in,
                              void* d_out, int out_size) {
    const float* inp    = (const float*)d_in[0];
    const float* flow   = (const float*)d_in[1];
    const float* metric = (const float*)d_in[2];
    float* out = (float*)d_out;

    zero_kernel<<<592, 256>>>();
    scatter_kernel<<<NHW / TILE, 256>>>(inp, flow, metric);   // 14336 blocks
    normalize_kernel<<<(NHW + 255) / 256, 256>>>(out);
}